// round 3
// baseline (speedup 1.0000x reference)
#include <cuda_runtime.h>
#include <math.h>

// ---------------- problem constants ----------------
constexpr int Tn = 1536;
constexpr int Cn = 1536;
constexpr int Hn = 8;
constexpr int Kn = 64;
constexpr int Vn = 192;
constexpr int Fn = 192;
constexpr int HK = Hn * Kn;   // 512
constexpr int HV = Hn * Vn;   // 1536
constexpr int L2 = 2 * Tn - 1; // 3071

// ---------------- scratch (static device globals; no allocation) ----------------
__device__ float g_xn[Tn * Cn];
__device__ float g_q[Tn * HK];
__device__ float g_qrw[Tn * HK];
__device__ float g_qrr[Tn * HK];
__device__ float g_k[Tn * HK];
__device__ float g_v[Tn * HV];
__device__ float g_pos[L2 * Fn];
__device__ float g_rk[L2 * HK];
__device__ float g_content[(size_t)Hn * Tn * Tn];  // reused as attn (softmax in-place)
__device__ float g_rel[(size_t)Hn * Tn * L2];
__device__ float g_o[Tn * HV];
__device__ float g_y[Tn * Cn];
__device__ float g_yn[Tn * Cn];
__device__ float g_h1[Tn * 2 * Cn];

// ---------------- tiled SGEMM: 128x128 tile, 8x8 microtile, 256 threads ----------------
// Double-buffered smem pipeline. C = alpha*A@op(B) (+bias)(+resid)(relu).
// op(B)=B[K,N] (NN) or B[N,K]^T (NT). Batched via blockIdx.z (element strides).
// K must be a multiple of 16 (here: 64,192,512,1536,3072). M/N edges predicated.
template <bool TRANSB>
__global__ __launch_bounds__(256, 2)
void gemm_kernel(const float* __restrict__ Ag, const float* __restrict__ Bg,
                 float* __restrict__ Cg, int M, int N, int Kd,
                 int lda, int ldb, int ldc,
                 long long aB, long long bB, long long cB,
                 const float* __restrict__ bias,
                 const float* __restrict__ resid,
                 int relu, float alpha) {
    const float* A = Ag + (long long)blockIdx.z * aB;
    const float* B = Bg + (long long)blockIdx.z * bB;
    float* C = Cg + (long long)blockIdx.z * cB;

    __shared__ float As[2][16][132];
    __shared__ float Bs[2][16][132];

    const int tid = threadIdx.x;          // 0..255
    const int m0 = blockIdx.y * 128;
    const int n0 = blockIdx.x * 128;
    const int tx = tid & 15;              // n dimension
    const int ty = tid >> 4;              // m dimension

    // A / NT-B load mapping: each thread fetches 8 consecutive-k elems of one row
    const int ldr = tid >> 1;             // row 0..127 within tile
    const int ldk = (tid & 1) << 3;       // k 0 or 8
    // NN-B load mapping: 16 k-rows x 128 cols; each thread 8 consecutive cols
    const int bro = tid >> 4;             // k row 0..15
    const int bco = (tid & 15) << 3;      // col 0..120

    float acc[8][8];
#pragma unroll
    for (int i = 0; i < 8; i++)
#pragma unroll
        for (int j = 0; j < 8; j++) acc[i][j] = 0.f;

    float pa[8], pb[8];

    auto loadA = [&](int k0) {
        int gm = m0 + ldr;
        if (gm < M) {
            const float* p = A + (long long)gm * lda + k0 + ldk;
#pragma unroll
            for (int u = 0; u < 8; u++) pa[u] = p[u];
        } else {
#pragma unroll
            for (int u = 0; u < 8; u++) pa[u] = 0.f;
        }
    };
    auto loadB = [&](int k0) {
        if (!TRANSB) {
            const float* p = B + (long long)(k0 + bro) * ldb + n0 + bco;
#pragma unroll
            for (int u = 0; u < 8; u++)
                pb[u] = (n0 + bco + u < N) ? p[u] : 0.f;
        } else {
            int gn = n0 + ldr;
            if (gn < N) {
                const float* p = B + (long long)gn * ldb + k0 + ldk;
#pragma unroll
                for (int u = 0; u < 8; u++) pb[u] = p[u];
            } else {
#pragma unroll
                for (int u = 0; u < 8; u++) pb[u] = 0.f;
            }
        }
    };
    auto store = [&](int buf) {
#pragma unroll
        for (int u = 0; u < 8; u++) As[buf][ldk + u][ldr] = pa[u];
        if (!TRANSB) {
#pragma unroll
            for (int u = 0; u < 8; u++) Bs[buf][bro][bco + u] = pb[u];
        } else {
#pragma unroll
            for (int u = 0; u < 8; u++) Bs[buf][ldk + u][ldr] = pb[u];
        }
    };
    auto compute = [&](int buf) {
#pragma unroll
        for (int kk = 0; kk < 16; kk++) {
            float a[8], b[8];
#pragma unroll
            for (int i = 0; i < 8; i++) a[i] = As[buf][kk][ty + 16 * i];  // warp broadcast
#pragma unroll
            for (int j = 0; j < 8; j++) b[j] = Bs[buf][kk][tx + 16 * j];  // conflict-free
#pragma unroll
            for (int i = 0; i < 8; i++)
#pragma unroll
                for (int j = 0; j < 8; j++) acc[i][j] += a[i] * b[j];
        }
    };

    // pipeline: prefetch k0, compute buf while loading k0+16 into the other buf
    loadA(0); loadB(0);
    store(0);
    __syncthreads();
    int buf = 0;
    for (int k0 = 16; k0 < Kd; k0 += 16) {
        loadA(k0); loadB(k0);
        compute(buf);
        store(buf ^ 1);
        __syncthreads();
        buf ^= 1;
    }
    compute(buf);

#pragma unroll
    for (int i = 0; i < 8; i++) {
        int gm = m0 + ty + 16 * i;
        if (gm >= M) continue;
#pragma unroll
        for (int j = 0; j < 8; j++) {
            int gn = n0 + tx + 16 * j;
            if (gn >= N) continue;
            float v = acc[i][j] * alpha;
            if (bias) v += bias[gn];
            if (resid) v += resid[(long long)gm * ldc + gn];
            if (relu) v = fmaxf(v, 0.f);
            C[(long long)gm * ldc + gn] = v;
        }
    }
}

// ---------------- LayerNorm (one block per row) ----------------
__global__ void layernorm_kernel(const float* __restrict__ x, const float* __restrict__ g,
                                 const float* __restrict__ b, float* __restrict__ out) {
    int row = blockIdx.x;
    const float* xr = x + (long long)row * Cn;
    float s = 0.f, ss = 0.f;
    for (int i = threadIdx.x; i < Cn; i += blockDim.x) {
        float v = xr[i];
        s += v;
        ss += v * v;
    }
    __shared__ float shs[32], shss[32];
    int lane = threadIdx.x & 31, w = threadIdx.x >> 5;
    for (int o = 16; o > 0; o >>= 1) {
        s += __shfl_xor_sync(0xffffffffu, s, o);
        ss += __shfl_xor_sync(0xffffffffu, ss, o);
    }
    if (lane == 0) { shs[w] = s; shss[w] = ss; }
    __syncthreads();
    int nw = blockDim.x >> 5;
    if (w == 0) {
        s = (lane < nw) ? shs[lane] : 0.f;
        ss = (lane < nw) ? shss[lane] : 0.f;
        for (int o = 16; o > 0; o >>= 1) {
            s += __shfl_xor_sync(0xffffffffu, s, o);
            ss += __shfl_xor_sync(0xffffffffu, ss, o);
        }
        if (lane == 0) { shs[0] = s; shss[0] = ss; }
    }
    __syncthreads();
    float mean = shs[0] / Cn;
    float var = shss[0] / Cn - mean * mean;
    float inv = rsqrtf(var + 1e-3f);
    float* orow = out + (long long)row * Cn;
    for (int i = threadIdx.x; i < Cn; i += blockDim.x)
        orow[i] = (xr[i] - mean) * inv * g[i] + b[i];
}

// ---------------- q + biases ----------------
__global__ void qbias_kernel(const float* __restrict__ q, const float* __restrict__ rwb,
                             const float* __restrict__ rrb, float* __restrict__ qrw,
                             float* __restrict__ qrr) {
    int idx = blockIdx.x * blockDim.x + threadIdx.x;
    if (idx < Tn * HK) {
        int c = idx % HK;
        float v = q[idx];
        qrw[idx] = v + rwb[c];
        qrr[idx] = v + rrb[c];
    }
}

// ---------------- positional features (block per position, 32 threads) ----------------
__global__ void posfeat_kernel(float* __restrict__ pos) {
    int l = blockIdx.x;       // 0..3070
    int i = threadIdx.x;      // 0..31
    float d = (float)(l - (Tn - 1));
    float ap = fabsf(d);

    // exponential half-life decay
    double start = 3.0, stop = log2((double)Tn);
    float hl = (float)exp2(start + (stop - start) * ((double)i / 31.0));
    float coef = (float)(-(log(2.0) / (double)hl));
    float fe = expf(ap * coef);

    // central mask
    float width = exp2f((float)(i + 1)) - 1.0f;
    float fcm = (width > ap) ? 1.f : 0.f;

    // gamma pdf bumps. xlogy(c-1, 0) = (c-1)*log(0) = -inf -> prob = 1e-8 at ap=0.
    // (must NOT guard the log at ap==0; the -inf is load-bearing)
    float conc = 4.0f * (float)((i + 1) * (i + 1));
    float rate = (float)(((double)(i + 1)) / 12.0);
    float log_unnorm = (conc - 1.0f) * logf(ap) - rate * ap;  // -inf at ap=0, by design
    float log_norm = lgammaf(conc) - conc * logf(rate);
    float prob = expf(log_unnorm - log_norm) + 1e-8f;

    float mx = prob;
    for (int o = 16; o > 0; o >>= 1) mx = fmaxf(mx, __shfl_xor_sync(0xffffffffu, mx, o));
    float fg = prob / mx;

    float sg = (d > 0.f) ? 1.f : ((d < 0.f) ? -1.f : 0.f);
    float* row = pos + (long long)l * Fn;
    row[i] = fe;
    row[32 + i] = fcm;
    row[64 + i] = fg;
    row[96 + i] = sg * fe;
    row[128 + i] = sg * fcm;
    row[160 + i] = sg * fg;
}

// ---------------- softmax with fused relative shift (in-place on content) ----------------
// logits[h,q,m] = content[h,q,m] + rel[h,q, m - q + T - 1]
__global__ void softmax_kernel(float* __restrict__ content, const float* __restrict__ rel) {
    int h = blockIdx.x / Tn, q = blockIdx.x % Tn;
    float* crow = content + ((long long)h * Tn + q) * Tn;
    const float* rrow = rel + ((long long)h * Tn + q) * (long long)L2 + (Tn - 1 - q);
    int t = threadIdx.x;  // 256 threads, 6 elems each
    float vals[6];
    float mx = -1e30f;
#pragma unroll
    for (int u = 0; u < 6; u++) {
        int m = t + u * 256;
        float v = crow[m] + rrow[m];
        vals[u] = v;
        mx = fmaxf(mx, v);
    }
    __shared__ float sh[32];
    int lane = t & 31, w = t >> 5;
    for (int o = 16; o > 0; o >>= 1) mx = fmaxf(mx, __shfl_xor_sync(0xffffffffu, mx, o));
    if (lane == 0) sh[w] = mx;
    __syncthreads();
    if (w == 0) {
        mx = (lane < 8) ? sh[lane] : -1e30f;
        for (int o = 16; o > 0; o >>= 1) mx = fmaxf(mx, __shfl_xor_sync(0xffffffffu, mx, o));
        if (lane == 0) sh[0] = mx;
    }
    __syncthreads();
    mx = sh[0];
    float tot = 0.f;
#pragma unroll
    for (int u = 0; u < 6; u++) {
        vals[u] = expf(vals[u] - mx);
        tot += vals[u];
    }
    __syncthreads();
    for (int o = 16; o > 0; o >>= 1) tot += __shfl_xor_sync(0xffffffffu, tot, o);
    if (lane == 0) sh[w] = tot;
    __syncthreads();
    if (w == 0) {
        tot = (lane < 8) ? sh[lane] : 0.f;
        for (int o = 16; o > 0; o >>= 1) tot += __shfl_xor_sync(0xffffffffu, tot, o);
        if (lane == 0) sh[0] = tot;
    }
    __syncthreads();
    float inv = 1.f / sh[0];
#pragma unroll
    for (int u = 0; u < 6; u++) crow[t + u * 256] = vals[u] * inv;
}

// ---------------- host orchestration ----------------
static void gemm(const float* A, const float* B, float* C, int M, int N, int Kd,
                 int lda, int ldb, int ldc,
                 long long aB, long long bB, long long cB, int batch, bool transB,
                 const float* bias, const float* resid, int relu, float alpha) {
    dim3 grid((N + 127) / 128, (M + 127) / 128, batch);
    if (transB)
        gemm_kernel<true><<<grid, 256>>>(A, B, C, M, N, Kd, lda, ldb, ldc, aB, bB, cB,
                                         bias, resid, relu, alpha);
    else
        gemm_kernel<false><<<grid, 256>>>(A, B, C, M, N, Kd, lda, ldb, ldc, aB, bB, cB,
                                          bias, resid, relu, alpha);
}

extern "C" void kernel_launch(void* const* d_in, const int* in_sizes, int n_in,
                              void* d_out, int out_size) {
    const float* x    = (const float*)d_in[0];
    const float* ln1g = (const float*)d_in[1];
    const float* ln1b = (const float*)d_in[2];
    const float* ln2g = (const float*)d_in[3];
    const float* ln2b = (const float*)d_in[4];
    const float* Wq   = (const float*)d_in[5];
    const float* Wk   = (const float*)d_in[6];
    const float* Wv   = (const float*)d_in[7];
    const float* Wr   = (const float*)d_in[8];
    const float* Wo   = (const float*)d_in[9];
    const float* bo   = (const float*)d_in[10];
    const float* rwb  = (const float*)d_in[11];
    const float* rrb  = (const float*)d_in[12];
    const float* W1   = (const float*)d_in[13];
    const float* b1   = (const float*)d_in[14];
    const float* W2   = (const float*)d_in[15];
    const float* b2   = (const float*)d_in[16];
    float* out = (float*)d_out;

    auto sym = [](const auto& s) {
        void* p = nullptr;
        cudaGetSymbolAddress(&p, s);
        return (float*)p;
    };
    float* xn = sym(g_xn);
    float* q = sym(g_q);
    float* qrw = sym(g_qrw);
    float* qrr = sym(g_qrr);
    float* k = sym(g_k);
    float* v = sym(g_v);
    float* pos = sym(g_pos);
    float* rk = sym(g_rk);
    float* content = sym(g_content);
    float* rel = sym(g_rel);
    float* o = sym(g_o);
    float* y = sym(g_y);
    float* yn = sym(g_yn);
    float* h1 = sym(g_h1);

    // 1) LN1
    layernorm_kernel<<<Tn, 256>>>(x, ln1g, ln1b, xn);
    // 2) Q (scaled by K^-0.5), K, V projections
    gemm(xn, Wq, q, Tn, HK, Cn, Cn, HK, HK, 0, 0, 0, 1, false, nullptr, nullptr, 0, 0.125f);
    gemm(xn, Wk, k, Tn, HK, Cn, Cn, HK, HK, 0, 0, 0, 1, false, nullptr, nullptr, 0, 1.f);
    gemm(xn, Wv, v, Tn, HV, Cn, Cn, HV, HV, 0, 0, 0, 1, false, nullptr, nullptr, 0, 1.f);
    // 3) q + r_w_bias / r_r_bias
    qbias_kernel<<<(Tn * HK + 255) / 256, 256>>>(q, rwb, rrb, qrw, qrr);
    // 4) positional features + projection
    posfeat_kernel<<<L2, 32>>>(pos);
    gemm(pos, Wr, rk, L2, HK, Fn, Fn, HK, HK, 0, 0, 0, 1, false, nullptr, nullptr, 0, 1.f);
    // 5) content logits: per-head (q+rwb) @ k^T   [H,T,T]
    gemm(qrw, k, content, Tn, Tn, Kn, HK, HK, Tn, 64, 64, (long long)Tn * Tn, Hn, true,
         nullptr, nullptr, 0, 1.f);
    // 6) relative logits: per-head (q+rrb) @ r_k^T  [H,T,2T-1]
    gemm(qrr, rk, rel, Tn, L2, Kn, HK, HK, L2, 64, 64, (long long)Tn * L2, Hn, true,
         nullptr, nullptr, 0, 1.f);
    // 7) softmax with fused relative shift (attn written in-place into content)
    softmax_kernel<<<Hn * Tn, 256>>>(content, rel);
    // 8) attn @ v -> o [T, H*V]
    gemm(content, v, o, Tn, Vn, Tn, Tn, HV, HV, (long long)Tn * Tn, 192, 192, Hn, false,
         nullptr, nullptr, 0, 1.f);
    // 9) out proj + residual:  y = x + o @ Wo + bo
    gemm(o, Wo, y, Tn, Cn, HV, HV, Cn, Cn, 0, 0, 0, 1, false, bo, x, 0, 1.f);
    // 10) LN2 + MLP
    layernorm_kernel<<<Tn, 256>>>(y, ln2g, ln2b, yn);
    gemm(yn, W1, h1, Tn, 2 * Cn, Cn, Cn, 2 * Cn, 2 * Cn, 0, 0, 0, 1, false, b1, nullptr, 1, 1.f);
    gemm(h1, W2, out, Tn, Cn, 2 * Cn, 2 * Cn, Cn, Cn, 0, 0, 0, 1, false, b2, y, 0, 1.f);
}

// round 4
// speedup vs baseline: 1.4847x; 1.4847x over previous
#include <cuda_runtime.h>
#include <math.h>

// ---------------- problem constants ----------------
constexpr int Tn = 1536;
constexpr int Cn = 1536;
constexpr int Hn = 8;
constexpr int Kn = 64;
constexpr int Vn = 192;
constexpr int Fn = 192;
constexpr int HK = Hn * Kn;   // 512
constexpr int HV = Hn * Vn;   // 1536
constexpr int L2 = 2 * Tn - 1; // 3071

// ---------------- scratch (static device globals; no allocation) ----------------
__device__ float g_xn[Tn * Cn];
__device__ float g_q[Tn * HK];
__device__ float g_qrw[Tn * HK];
__device__ float g_qrr[Tn * HK];
__device__ float g_k[Tn * HK];
__device__ float g_v[Tn * HV];
__device__ float g_pos[L2 * Fn];
__device__ float g_rk[L2 * HK];
__device__ float g_content[(size_t)Hn * Tn * Tn];  // reused as attn (softmax in-place)
__device__ float g_rel[(size_t)Hn * Tn * L2];
__device__ float g_o[Tn * HV];
__device__ float g_y[Tn * Cn];
__device__ float g_yn[Tn * Cn];
__device__ float g_h1[Tn * 2 * Cn];

// ---------------- tiled SGEMM: 128x128 tile, 8x8 microtile, 256 threads ----------------
// Double-buffered; float4 global loads (coalesced) + float4 smem fragment loads.
// C = alpha*A@op(B) (+bias)(+resid)(relu). op(B)=B[K,N] (NN) or B[N,K]^T (NT).
// Batched via blockIdx.z (element strides). K % 16 == 0 (here: 64,192,512,1536,3072).
// All lda/ldb/batch offsets are multiples of 4 floats (16B) — verified per call site.
// N % 4 == 0 so float4 N-edge predication is all-or-nothing.
template <bool TRANSB>
__global__ __launch_bounds__(256, 2)
void gemm_kernel(const float* __restrict__ Ag, const float* __restrict__ Bg,
                 float* __restrict__ Cg, int M, int N, int Kd,
                 int lda, int ldb, int ldc,
                 long long aB, long long bB, long long cB,
                 const float* __restrict__ bias,
                 const float* __restrict__ resid,
                 int relu, float alpha) {
    const float* A = Ag + (long long)blockIdx.z * aB;
    const float* B = Bg + (long long)blockIdx.z * bB;
    float* C = Cg + (long long)blockIdx.z * cB;

    __shared__ float As[2][16][132];
    __shared__ float Bs[2][16][132];

    const int tid = threadIdx.x;          // 0..255
    const int m0 = blockIdx.y * 128;
    const int n0 = blockIdx.x * 128;
    const int tx = tid & 15;              // n quad index
    const int ty = tid >> 4;              // m quad index

    // A (and NT-B) load mapping: float4 along k
    const int ar = tid >> 2;              // row 0..63 (and +64)
    const int ak = tid & 3;               // k-quad 0..3 (k offset ak*4)
    // NN-B load mapping: float4 along n
    const int bkr = tid >> 5;             // k row 0..7 (and +8)
    const int bcq = tid & 31;             // col-quad 0..31 (col offset bcq*4)

    float acc[8][8];
#pragma unroll
    for (int i = 0; i < 8; i++)
#pragma unroll
        for (int j = 0; j < 8; j++) acc[i][j] = 0.f;

    const float4 zero4 = make_float4(0.f, 0.f, 0.f, 0.f);
    float4 pa0, pa1, pb0, pb1;

    auto loadA = [&](int k0) {
        int gm0 = m0 + ar, gm1 = gm0 + 64;
        pa0 = (gm0 < M) ? *(const float4*)(A + (long long)gm0 * lda + k0 + ak * 4) : zero4;
        pa1 = (gm1 < M) ? *(const float4*)(A + (long long)gm1 * lda + k0 + ak * 4) : zero4;
    };
    auto loadB = [&](int k0) {
        if (!TRANSB) {
            int gn = n0 + bcq * 4;
            pb0 = (gn < N) ? *(const float4*)(B + (long long)(k0 + bkr) * ldb + gn) : zero4;
            pb1 = (gn < N) ? *(const float4*)(B + (long long)(k0 + bkr + 8) * ldb + gn) : zero4;
        } else {
            int gn0 = n0 + ar, gn1 = gn0 + 64;
            pb0 = (gn0 < N) ? *(const float4*)(B + (long long)gn0 * ldb + k0 + ak * 4) : zero4;
            pb1 = (gn1 < N) ? *(const float4*)(B + (long long)gn1 * ldb + k0 + ak * 4) : zero4;
        }
    };
    auto store = [&](int buf) {
        // A: transposed scalar stores As[k][m]
        As[buf][ak * 4 + 0][ar] = pa0.x;
        As[buf][ak * 4 + 1][ar] = pa0.y;
        As[buf][ak * 4 + 2][ar] = pa0.z;
        As[buf][ak * 4 + 3][ar] = pa0.w;
        As[buf][ak * 4 + 0][ar + 64] = pa1.x;
        As[buf][ak * 4 + 1][ar + 64] = pa1.y;
        As[buf][ak * 4 + 2][ar + 64] = pa1.z;
        As[buf][ak * 4 + 3][ar + 64] = pa1.w;
        if (!TRANSB) {
            *(float4*)&Bs[buf][bkr][bcq * 4] = pb0;
            *(float4*)&Bs[buf][bkr + 8][bcq * 4] = pb1;
        } else {
            Bs[buf][ak * 4 + 0][ar] = pb0.x;
            Bs[buf][ak * 4 + 1][ar] = pb0.y;
            Bs[buf][ak * 4 + 2][ar] = pb0.z;
            Bs[buf][ak * 4 + 3][ar] = pb0.w;
            Bs[buf][ak * 4 + 0][ar + 64] = pb1.x;
            Bs[buf][ak * 4 + 1][ar + 64] = pb1.y;
            Bs[buf][ak * 4 + 2][ar + 64] = pb1.z;
            Bs[buf][ak * 4 + 3][ar + 64] = pb1.w;
        }
    };
    auto compute = [&](int buf) {
#pragma unroll
        for (int kk = 0; kk < 16; kk++) {
            float4 a0 = *(const float4*)&As[buf][kk][ty * 4];
            float4 a1 = *(const float4*)&As[buf][kk][64 + ty * 4];
            float4 b0 = *(const float4*)&Bs[buf][kk][tx * 4];
            float4 b1 = *(const float4*)&Bs[buf][kk][64 + tx * 4];
            const float a[8] = {a0.x, a0.y, a0.z, a0.w, a1.x, a1.y, a1.z, a1.w};
            const float b[8] = {b0.x, b0.y, b0.z, b0.w, b1.x, b1.y, b1.z, b1.w};
#pragma unroll
            for (int i = 0; i < 8; i++)
#pragma unroll
                for (int j = 0; j < 8; j++) acc[i][j] += a[i] * b[j];
        }
    };

    loadA(0); loadB(0);
    store(0);
    __syncthreads();
    int buf = 0;
    for (int k0 = 16; k0 < Kd; k0 += 16) {
        loadA(k0); loadB(k0);
        compute(buf);
        store(buf ^ 1);
        __syncthreads();
        buf ^= 1;
    }
    compute(buf);

#pragma unroll
    for (int hi = 0; hi < 2; hi++)
#pragma unroll
        for (int ii = 0; ii < 4; ii++) {
            int gm = m0 + hi * 64 + ty * 4 + ii;
            if (gm >= M) continue;
#pragma unroll
            for (int hj = 0; hj < 2; hj++)
#pragma unroll
                for (int jj = 0; jj < 4; jj++) {
                    int gn = n0 + hj * 64 + tx * 4 + jj;
                    if (gn >= N) continue;
                    float v = acc[hi * 4 + ii][hj * 4 + jj] * alpha;
                    if (bias) v += bias[gn];
                    if (resid) v += resid[(long long)gm * ldc + gn];
                    if (relu) v = fmaxf(v, 0.f);
                    C[(long long)gm * ldc + gn] = v;
                }
        }
}

// ---------------- LayerNorm (one block per row) ----------------
__global__ void layernorm_kernel(const float* __restrict__ x, const float* __restrict__ g,
                                 const float* __restrict__ b, float* __restrict__ out) {
    int row = blockIdx.x;
    const float* xr = x + (long long)row * Cn;
    float s = 0.f, ss = 0.f;
    for (int i = threadIdx.x; i < Cn; i += blockDim.x) {
        float v = xr[i];
        s += v;
        ss += v * v;
    }
    __shared__ float shs[32], shss[32];
    int lane = threadIdx.x & 31, w = threadIdx.x >> 5;
    for (int o = 16; o > 0; o >>= 1) {
        s += __shfl_xor_sync(0xffffffffu, s, o);
        ss += __shfl_xor_sync(0xffffffffu, ss, o);
    }
    if (lane == 0) { shs[w] = s; shss[w] = ss; }
    __syncthreads();
    int nw = blockDim.x >> 5;
    if (w == 0) {
        s = (lane < nw) ? shs[lane] : 0.f;
        ss = (lane < nw) ? shss[lane] : 0.f;
        for (int o = 16; o > 0; o >>= 1) {
            s += __shfl_xor_sync(0xffffffffu, s, o);
            ss += __shfl_xor_sync(0xffffffffu, ss, o);
        }
        if (lane == 0) { shs[0] = s; shss[0] = ss; }
    }
    __syncthreads();
    float mean = shs[0] / Cn;
    float var = shss[0] / Cn - mean * mean;
    float inv = rsqrtf(var + 1e-3f);
    float* orow = out + (long long)row * Cn;
    for (int i = threadIdx.x; i < Cn; i += blockDim.x)
        orow[i] = (xr[i] - mean) * inv * g[i] + b[i];
}

// ---------------- q + biases ----------------
__global__ void qbias_kernel(const float* __restrict__ q, const float* __restrict__ rwb,
                             const float* __restrict__ rrb, float* __restrict__ qrw,
                             float* __restrict__ qrr) {
    int idx = blockIdx.x * blockDim.x + threadIdx.x;
    if (idx < Tn * HK) {
        int c = idx % HK;
        float v = q[idx];
        qrw[idx] = v + rwb[c];
        qrr[idx] = v + rrb[c];
    }
}

// ---------------- positional features (block per position, 32 threads) ----------------
__global__ void posfeat_kernel(float* __restrict__ pos) {
    int l = blockIdx.x;       // 0..3070
    int i = threadIdx.x;      // 0..31
    float d = (float)(l - (Tn - 1));
    float ap = fabsf(d);

    // exponential half-life decay
    double start = 3.0, stop = log2((double)Tn);
    float hl = (float)exp2(start + (stop - start) * ((double)i / 31.0));
    float coef = (float)(-(log(2.0) / (double)hl));
    float fe = expf(ap * coef);

    // central mask
    float width = exp2f((float)(i + 1)) - 1.0f;
    float fcm = (width > ap) ? 1.f : 0.f;

    // gamma pdf bumps. xlogy(c-1, 0) = (c-1)*log(0) = -inf -> prob = 1e-8 at ap=0.
    // (must NOT guard the log at ap==0; the -inf is load-bearing)
    float conc = 4.0f * (float)((i + 1) * (i + 1));
    float rate = (float)(((double)(i + 1)) / 12.0);
    float log_unnorm = (conc - 1.0f) * logf(ap) - rate * ap;  // -inf at ap=0, by design
    float log_norm = lgammaf(conc) - conc * logf(rate);
    float prob = expf(log_unnorm - log_norm) + 1e-8f;

    float mx = prob;
    for (int o = 16; o > 0; o >>= 1) mx = fmaxf(mx, __shfl_xor_sync(0xffffffffu, mx, o));
    float fg = prob / mx;

    float sg = (d > 0.f) ? 1.f : ((d < 0.f) ? -1.f : 0.f);
    float* row = pos + (long long)l * Fn;
    row[i] = fe;
    row[32 + i] = fcm;
    row[64 + i] = fg;
    row[96 + i] = sg * fe;
    row[128 + i] = sg * fcm;
    row[160 + i] = sg * fg;
}

// ---------------- softmax with fused relative shift (in-place on content) ----------------
// logits[h,q,m] = content[h,q,m] + rel[h,q, m - q + T - 1]
__global__ void softmax_kernel(float* __restrict__ content, const float* __restrict__ rel) {
    int h = blockIdx.x / Tn, q = blockIdx.x % Tn;
    float* crow = content + ((long long)h * Tn + q) * Tn;
    const float* rrow = rel + ((long long)h * Tn + q) * (long long)L2 + (Tn - 1 - q);
    int t = threadIdx.x;  // 256 threads, 6 elems each
    float vals[6];
    float mx = -1e30f;
#pragma unroll
    for (int u = 0; u < 6; u++) {
        int m = t + u * 256;
        float v = crow[m] + rrow[m];
        vals[u] = v;
        mx = fmaxf(mx, v);
    }
    __shared__ float sh[32];
    int lane = t & 31, w = t >> 5;
    for (int o = 16; o > 0; o >>= 1) mx = fmaxf(mx, __shfl_xor_sync(0xffffffffu, mx, o));
    if (lane == 0) sh[w] = mx;
    __syncthreads();
    if (w == 0) {
        mx = (lane < 8) ? sh[lane] : -1e30f;
        for (int o = 16; o > 0; o >>= 1) mx = fmaxf(mx, __shfl_xor_sync(0xffffffffu, mx, o));
        if (lane == 0) sh[0] = mx;
    }
    __syncthreads();
    mx = sh[0];
    float tot = 0.f;
#pragma unroll
    for (int u = 0; u < 6; u++) {
        vals[u] = expf(vals[u] - mx);
        tot += vals[u];
    }
    __syncthreads();
    for (int o = 16; o > 0; o >>= 1) tot += __shfl_xor_sync(0xffffffffu, tot, o);
    if (lane == 0) sh[w] = tot;
    __syncthreads();
    if (w == 0) {
        tot = (lane < 8) ? sh[lane] : 0.f;
        for (int o = 16; o > 0; o >>= 1) tot += __shfl_xor_sync(0xffffffffu, tot, o);
        if (lane == 0) sh[0] = tot;
    }
    __syncthreads();
    float inv = 1.f / sh[0];
#pragma unroll
    for (int u = 0; u < 6; u++) crow[t + u * 256] = vals[u] * inv;
}

// ---------------- host orchestration ----------------
static void gemm(const float* A, const float* B, float* C, int M, int N, int Kd,
                 int lda, int ldb, int ldc,
                 long long aB, long long bB, long long cB, int batch, bool transB,
                 const float* bias, const float* resid, int relu, float alpha) {
    dim3 grid((N + 127) / 128, (M + 127) / 128, batch);
    if (transB)
        gemm_kernel<true><<<grid, 256>>>(A, B, C, M, N, Kd, lda, ldb, ldc, aB, bB, cB,
                                         bias, resid, relu, alpha);
    else
        gemm_kernel<false><<<grid, 256>>>(A, B, C, M, N, Kd, lda, ldb, ldc, aB, bB, cB,
                                          bias, resid, relu, alpha);
}

extern "C" void kernel_launch(void* const* d_in, const int* in_sizes, int n_in,
                              void* d_out, int out_size) {
    const float* x    = (const float*)d_in[0];
    const float* ln1g = (const float*)d_in[1];
    const float* ln1b = (const float*)d_in[2];
    const float* ln2g = (const float*)d_in[3];
    const float* ln2b = (const float*)d_in[4];
    const float* Wq   = (const float*)d_in[5];
    const float* Wk   = (const float*)d_in[6];
    const float* Wv   = (const float*)d_in[7];
    const float* Wr   = (const float*)d_in[8];
    const float* Wo   = (const float*)d_in[9];
    const float* bo   = (const float*)d_in[10];
    const float* rwb  = (const float*)d_in[11];
    const float* rrb  = (const float*)d_in[12];
    const float* W1   = (const float*)d_in[13];
    const float* b1   = (const float*)d_in[14];
    const float* W2   = (const float*)d_in[15];
    const float* b2   = (const float*)d_in[16];
    float* out = (float*)d_out;

    auto sym = [](const auto& s) {
        void* p = nullptr;
        cudaGetSymbolAddress(&p, s);
        return (float*)p;
    };
    float* xn = sym(g_xn);
    float* q = sym(g_q);
    float* qrw = sym(g_qrw);
    float* qrr = sym(g_qrr);
    float* k = sym(g_k);
    float* v = sym(g_v);
    float* pos = sym(g_pos);
    float* rk = sym(g_rk);
    float* content = sym(g_content);
    float* rel = sym(g_rel);
    float* o = sym(g_o);
    float* y = sym(g_y);
    float* yn = sym(g_yn);
    float* h1 = sym(g_h1);

    // 1) LN1
    layernorm_kernel<<<Tn, 256>>>(x, ln1g, ln1b, xn);
    // 2) Q (scaled by K^-0.5), K, V projections
    gemm(xn, Wq, q, Tn, HK, Cn, Cn, HK, HK, 0, 0, 0, 1, false, nullptr, nullptr, 0, 0.125f);
    gemm(xn, Wk, k, Tn, HK, Cn, Cn, HK, HK, 0, 0, 0, 1, false, nullptr, nullptr, 0, 1.f);
    gemm(xn, Wv, v, Tn, HV, Cn, Cn, HV, HV, 0, 0, 0, 1, false, nullptr, nullptr, 0, 1.f);
    // 3) q + r_w_bias / r_r_bias
    qbias_kernel<<<(Tn * HK + 255) / 256, 256>>>(q, rwb, rrb, qrw, qrr);
    // 4) positional features + projection
    posfeat_kernel<<<L2, 32>>>(pos);
    gemm(pos, Wr, rk, L2, HK, Fn, Fn, HK, HK, 0, 0, 0, 1, false, nullptr, nullptr, 0, 1.f);
    // 5) content logits: per-head (q+rwb) @ k^T   [H,T,T]
    gemm(qrw, k, content, Tn, Tn, Kn, HK, HK, Tn, 64, 64, (long long)Tn * Tn, Hn, true,
         nullptr, nullptr, 0, 1.f);
    // 6) relative logits: per-head (q+rrb) @ r_k^T  [H,T,2T-1]
    gemm(qrr, rk, rel, Tn, L2, Kn, HK, HK, L2, 64, 64, (long long)Tn * L2, Hn, true,
         nullptr, nullptr, 0, 1.f);
    // 7) softmax with fused relative shift (attn written in-place into content)
    softmax_kernel<<<Hn * Tn, 256>>>(content, rel);
    // 8) attn @ v -> o [T, H*V]
    gemm(content, v, o, Tn, Vn, Tn, Tn, HV, HV, (long long)Tn * Tn, 192, 192, Hn, false,
         nullptr, nullptr, 0, 1.f);
    // 9) out proj + residual:  y = x + o @ Wo + bo
    gemm(o, Wo, y, Tn, Cn, HV, HV, Cn, Cn, 0, 0, 0, 1, false, bo, x, 0, 1.f);
    // 10) LN2 + MLP
    layernorm_kernel<<<Tn, 256>>>(y, ln2g, ln2b, yn);
    gemm(yn, W1, h1, Tn, 2 * Cn, Cn, Cn, 2 * Cn, 2 * Cn, 0, 0, 0, 1, false, b1, nullptr, 1, 1.f);
    gemm(h1, W2, out, Tn, Cn, 2 * Cn, 2 * Cn, Cn, Cn, 0, 0, 0, 1, false, b2, y, 0, 1.f);
}

// round 5
// speedup vs baseline: 2.0476x; 1.3792x over previous
#include <cuda_runtime.h>
#include <cuda_bf16.h>
#include <math.h>
#include <stdint.h>

// ---------------- problem constants ----------------
constexpr int Tn = 1536;
constexpr int Cn = 1536;
constexpr int Hn = 8;
constexpr int Kn = 64;
constexpr int Vn = 192;
constexpr int Fn = 192;
constexpr int HK = Hn * Kn;   // 512
constexpr int HV = Hn * Vn;   // 1536
constexpr int L2 = 2 * Tn - 1; // 3071

// ---------------- scratch (static device globals; no allocation) ----------------
__device__ float g_xn[Tn * Cn];
__device__ float g_q[Tn * HK];
__device__ float g_qrw[Tn * HK];
__device__ float g_qrr[Tn * HK];
__device__ float g_k[Tn * HK];
__device__ float g_v[Tn * HV];
__device__ float g_pos[L2 * Fn];
__device__ float g_rk[L2 * HK];
__device__ float g_content[(size_t)Hn * Tn * Tn];  // reused as attn (softmax in-place)
__device__ float g_rel[(size_t)Hn * Tn * L2];
__device__ float g_o[Tn * HV];
__device__ float g_y[Tn * Cn];
__device__ float g_yn[Tn * Cn];
__device__ float g_h1[Tn * 2 * Cn];

// ---------------- bf16 split-precision tensor-core GEMM ----------------
// C = alpha*A@op(B) (+bias)(+resid)(relu), fp32 in/out.
// Each fp32 x is split x = hi + lo (bf16 each); C uses Ahi*Bhi + Ahi*Blo + Alo*Bhi
// (error ~2^-16 per term). Tile 128x128, k-tile 32 fp32, 256 threads (8 warps,
// warp grid 2m x 4n, warp tile 64x32), mma.sync.m16n8k16.
// smem layout per matrix: [128 rows][72 bf16] where cols 0..31 = hi, 32..63 = lo.
// Row stride 72 bf16 = 144B => conflict-free fragment LDS.
// Batched via blockIdx.z (element strides). K%32==0 (64,192,512,1536,3072).
// NN path requires N%16==0 (all NN call sites comply); NT path predicates per row.
constexpr int GPITCH = 72;
constexpr int GTILE = 128 * GPITCH;           // bf16 elems per buffer per matrix
constexpr int GSMEM_BYTES = 4 * GTILE * 2;    // A[2] + B[2]

__device__ __forceinline__ uint32_t pack2bf(float x, float y) {
    __nv_bfloat162 h = __floats2bfloat162_rn(x, y);
    return *(uint32_t*)&h;
}

__device__ __forceinline__ void mma16816(float* c, uint32_t a0, uint32_t a1,
                                         uint32_t a2, uint32_t a3,
                                         uint32_t b0, uint32_t b1) {
    asm volatile(
        "mma.sync.aligned.m16n8k16.row.col.f32.bf16.bf16.f32 "
        "{%0,%1,%2,%3}, {%4,%5,%6,%7}, {%8,%9}, {%0,%1,%2,%3};\n"
        : "+f"(c[0]), "+f"(c[1]), "+f"(c[2]), "+f"(c[3])
        : "r"(a0), "r"(a1), "r"(a2), "r"(a3), "r"(b0), "r"(b1));
}

template <bool TRANSB>
__global__ __launch_bounds__(256)
void gemm_kernel(const float* __restrict__ Ag, const float* __restrict__ Bg,
                 float* __restrict__ Cg, int M, int N, int Kd,
                 int lda, int ldb, int ldc,
                 long long aB, long long bB, long long cB,
                 const float* __restrict__ bias,
                 const float* __restrict__ resid,
                 int relu, float alpha) {
    extern __shared__ __nv_bfloat16 sm[];
    __nv_bfloat16* Asm = sm;               // [2][128][GPITCH]
    __nv_bfloat16* Bsm = sm + 2 * GTILE;   // [2][128][GPITCH] (indexed by n)

    const float* A = Ag + (long long)blockIdx.z * aB;
    const float* B = Bg + (long long)blockIdx.z * bB;
    float* C = Cg + (long long)blockIdx.z * cB;

    const int tid = threadIdx.x;
    const int lane = tid & 31;
    const int warp = tid >> 5;
    const int wm = warp & 1;     // m offset wm*64
    const int wn = warp >> 1;    // n offset wn*32
    const int g = lane >> 2;     // fragment group row/col
    const int th = lane & 3;     // fragment k pair index
    const int m0 = blockIdx.y * 128;
    const int n0 = blockIdx.x * 128;

    // ---- global load mappings ----
    // A / NT-B: 2 threads per row; each loads 16 consecutive floats (4 float4)
    const int arow = tid >> 1;               // 0..127
    const int acol = (tid & 1) * 16;         // 0 or 16
    // NN-B: 8 threads per k-row; each loads 16 consecutive floats
    const int bkr = tid >> 3;                // 0..31
    const int bnq = (tid & 7) * 16;          // 0..112

    float acc[4][4][4];
#pragma unroll
    for (int i = 0; i < 4; i++)
#pragma unroll
        for (int j = 0; j < 4; j++)
#pragma unroll
            for (int c = 0; c < 4; c++) acc[i][j][c] = 0.f;

    const float4 zero4 = make_float4(0.f, 0.f, 0.f, 0.f);
    float4 va[4], vb[4];

    auto loadA = [&](int k0) {
        int gm = m0 + arow;
        if (gm < M) {
            const float4* p = (const float4*)(A + (long long)gm * lda + k0 + acol);
#pragma unroll
            for (int q = 0; q < 4; q++) va[q] = p[q];
        } else {
#pragma unroll
            for (int q = 0; q < 4; q++) va[q] = zero4;
        }
    };
    auto loadB = [&](int k0) {
        if (!TRANSB) {
            int gn = n0 + bnq;   // N%16==0 so the 16-col chunk is all-in or all-out
            if (gn < N) {
                const float4* p = (const float4*)(B + (long long)(k0 + bkr) * ldb + gn);
#pragma unroll
                for (int q = 0; q < 4; q++) vb[q] = p[q];
            } else {
#pragma unroll
                for (int q = 0; q < 4; q++) vb[q] = zero4;
            }
        } else {
            int gn = n0 + arow;
            if (gn < N) {
                const float4* p = (const float4*)(B + (long long)gn * ldb + k0 + acol);
#pragma unroll
                for (int q = 0; q < 4; q++) vb[q] = p[q];
            } else {
#pragma unroll
                for (int q = 0; q < 4; q++) vb[q] = zero4;
            }
        }
    };
    // split one fp32 into (hi, lo) bf16
    auto split = [](float x, float& lo) -> __nv_bfloat16 {
        __nv_bfloat16 h = __float2bfloat16(x);
        lo = x - __bfloat162float(h);
        return h;
    };
    // store 16 floats (4 float4) as hi/lo into row `row` at cols colbase..+15
    auto storeRow = [&](__nv_bfloat16* base, int row, int colbase, const float4* v) {
        uint32_t* hp = (uint32_t*)(base + row * GPITCH + colbase);
        uint32_t* lp = (uint32_t*)(base + row * GPITCH + 32 + colbase);
#pragma unroll
        for (int q = 0; q < 4; q++) {
            float l0, l1, l2, l3;
            __nv_bfloat16 h0 = split(v[q].x, l0), h1 = split(v[q].y, l1);
            __nv_bfloat16 h2 = split(v[q].z, l2), h3 = split(v[q].w, l3);
            hp[q * 2 + 0] = pack2bf(__bfloat162float(h0), __bfloat162float(h1));
            hp[q * 2 + 1] = pack2bf(__bfloat162float(h2), __bfloat162float(h3));
            lp[q * 2 + 0] = pack2bf(l0, l1);
            lp[q * 2 + 1] = pack2bf(l2, l3);
        }
    };
    auto storeA = [&](int buf) { storeRow(Asm + buf * GTILE, arow, acol, va); };
    auto storeB = [&](int buf) {
        if (!TRANSB) {
            // transpose to Bsm[n][k]
            __nv_bfloat16* base = Bsm + buf * GTILE;
            const float* f = (const float*)vb;
#pragma unroll
            for (int ii = 0; ii < 16; ii++) {
                int i = (ii + ((tid & 7) * 2)) & 15;  // stagger to reduce conflicts
                float lo;
                __nv_bfloat16 hi = split(f[i], lo);
                base[(bnq + i) * GPITCH + bkr] = hi;
                base[(bnq + i) * GPITCH + 32 + bkr] = __float2bfloat16(lo);
            }
        } else {
            storeRow(Bsm + buf * GTILE, arow, acol, vb);
        }
    };

    // compute one k16 step with A cols ca, B cols cb
    auto step = [&](const __nv_bfloat16* Ab, const __nv_bfloat16* Bb, int ca, int cb) {
        uint32_t bfr[4][2];
#pragma unroll
        for (int j = 0; j < 4; j++) {
            const uint32_t* p = (const uint32_t*)(Bb + (wn * 32 + j * 8 + g) * GPITCH + cb + th * 2);
            bfr[j][0] = p[0];
            bfr[j][1] = p[4];
        }
#pragma unroll
        for (int i = 0; i < 4; i++) {
            int r = wm * 64 + i * 16 + g;
            const uint32_t* p0 = (const uint32_t*)(Ab + r * GPITCH + ca + th * 2);
            const uint32_t* p1 = (const uint32_t*)(Ab + (r + 8) * GPITCH + ca + th * 2);
            uint32_t a0 = p0[0], a2 = p0[4];
            uint32_t a1 = p1[0], a3 = p1[4];
#pragma unroll
            for (int j = 0; j < 4; j++)
                mma16816(acc[i][j], a0, a1, a2, a3, bfr[j][0], bfr[j][1]);
        }
    };
    auto compute = [&](int buf) {
        const __nv_bfloat16* Ab = Asm + buf * GTILE;
        const __nv_bfloat16* Bb = Bsm + buf * GTILE;
        // hi*hi (two k16 blocks), hi*lo, lo*hi
        step(Ab, Bb, 0, 0);
        step(Ab, Bb, 16, 16);
        step(Ab, Bb, 0, 32);
        step(Ab, Bb, 16, 48);
        step(Ab, Bb, 32, 0);
        step(Ab, Bb, 48, 16);
    };

    loadA(0); loadB(0);
    storeA(0); storeB(0);
    __syncthreads();
    int buf = 0;
    for (int k0 = 32; k0 < Kd; k0 += 32) {
        loadA(k0); loadB(k0);
        compute(buf);
        storeA(buf ^ 1); storeB(buf ^ 1);
        __syncthreads();
        buf ^= 1;
    }
    compute(buf);

    // ---- epilogue ----
#pragma unroll
    for (int i = 0; i < 4; i++) {
        int rbase = m0 + wm * 64 + i * 16 + g;
#pragma unroll
        for (int j = 0; j < 4; j++) {
            int cbase = n0 + wn * 32 + j * 8 + th * 2;
#pragma unroll
            for (int c = 0; c < 4; c++) {
                int gm = rbase + (c >> 1) * 8;
                int gn = cbase + (c & 1);
                if (gm >= M || gn >= N) continue;
                float v = acc[i][j][c] * alpha;
                if (bias) v += bias[gn];
                if (resid) v += resid[(long long)gm * ldc + gn];
                if (relu) v = fmaxf(v, 0.f);
                C[(long long)gm * ldc + gn] = v;
            }
        }
    }
}

// ---------------- LayerNorm (one block per row) ----------------
__global__ void layernorm_kernel(const float* __restrict__ x, const float* __restrict__ g,
                                 const float* __restrict__ b, float* __restrict__ out) {
    int row = blockIdx.x;
    const float* xr = x + (long long)row * Cn;
    float s = 0.f, ss = 0.f;
    for (int i = threadIdx.x; i < Cn; i += blockDim.x) {
        float v = xr[i];
        s += v;
        ss += v * v;
    }
    __shared__ float shs[32], shss[32];
    int lane = threadIdx.x & 31, w = threadIdx.x >> 5;
    for (int o = 16; o > 0; o >>= 1) {
        s += __shfl_xor_sync(0xffffffffu, s, o);
        ss += __shfl_xor_sync(0xffffffffu, ss, o);
    }
    if (lane == 0) { shs[w] = s; shss[w] = ss; }
    __syncthreads();
    int nw = blockDim.x >> 5;
    if (w == 0) {
        s = (lane < nw) ? shs[lane] : 0.f;
        ss = (lane < nw) ? shss[lane] : 0.f;
        for (int o = 16; o > 0; o >>= 1) {
            s += __shfl_xor_sync(0xffffffffu, s, o);
            ss += __shfl_xor_sync(0xffffffffu, ss, o);
        }
        if (lane == 0) { shs[0] = s; shss[0] = ss; }
    }
    __syncthreads();
    float mean = shs[0] / Cn;
    float var = shss[0] / Cn - mean * mean;
    float inv = rsqrtf(var + 1e-3f);
    float* orow = out + (long long)row * Cn;
    for (int i = threadIdx.x; i < Cn; i += blockDim.x)
        orow[i] = (xr[i] - mean) * inv * g[i] + b[i];
}

// ---------------- q + biases ----------------
__global__ void qbias_kernel(const float* __restrict__ q, const float* __restrict__ rwb,
                             const float* __restrict__ rrb, float* __restrict__ qrw,
                             float* __restrict__ qrr) {
    int idx = blockIdx.x * blockDim.x + threadIdx.x;
    if (idx < Tn * HK) {
        int c = idx % HK;
        float v = q[idx];
        qrw[idx] = v + rwb[c];
        qrr[idx] = v + rrb[c];
    }
}

// ---------------- positional features (block per position, 32 threads) ----------------
__global__ void posfeat_kernel(float* __restrict__ pos) {
    int l = blockIdx.x;       // 0..3070
    int i = threadIdx.x;      // 0..31
    float d = (float)(l - (Tn - 1));
    float ap = fabsf(d);

    // exponential half-life decay
    double start = 3.0, stop = log2((double)Tn);
    float hl = (float)exp2(start + (stop - start) * ((double)i / 31.0));
    float coef = (float)(-(log(2.0) / (double)hl));
    float fe = expf(ap * coef);

    // central mask
    float width = exp2f((float)(i + 1)) - 1.0f;
    float fcm = (width > ap) ? 1.f : 0.f;

    // gamma pdf bumps. xlogy(c-1, 0) = (c-1)*log(0) = -inf -> prob = 1e-8 at ap=0.
    // (must NOT guard the log at ap==0; the -inf is load-bearing)
    float conc = 4.0f * (float)((i + 1) * (i + 1));
    float rate = (float)(((double)(i + 1)) / 12.0);
    float log_unnorm = (conc - 1.0f) * logf(ap) - rate * ap;  // -inf at ap=0, by design
    float log_norm = lgammaf(conc) - conc * logf(rate);
    float prob = expf(log_unnorm - log_norm) + 1e-8f;

    float mx = prob;
    for (int o = 16; o > 0; o >>= 1) mx = fmaxf(mx, __shfl_xor_sync(0xffffffffu, mx, o));
    float fg = prob / mx;

    float sg = (d > 0.f) ? 1.f : ((d < 0.f) ? -1.f : 0.f);
    float* row = pos + (long long)l * Fn;
    row[i] = fe;
    row[32 + i] = fcm;
    row[64 + i] = fg;
    row[96 + i] = sg * fe;
    row[128 + i] = sg * fcm;
    row[160 + i] = sg * fg;
}

// ---------------- softmax with fused relative shift (in-place on content) ----------------
// logits[h,q,m] = content[h,q,m] + rel[h,q, m - q + T - 1]
__global__ void softmax_kernel(float* __restrict__ content, const float* __restrict__ rel) {
    int h = blockIdx.x / Tn, q = blockIdx.x % Tn;
    float* crow = content + ((long long)h * Tn + q) * Tn;
    const float* rrow = rel + ((long long)h * Tn + q) * (long long)L2 + (Tn - 1 - q);
    int t = threadIdx.x;  // 256 threads, 6 elems each
    float vals[6];
    float mx = -1e30f;
#pragma unroll
    for (int u = 0; u < 6; u++) {
        int m = t + u * 256;
        float v = crow[m] + rrow[m];
        vals[u] = v;
        mx = fmaxf(mx, v);
    }
    __shared__ float sh[32];
    int lane = t & 31, w = t >> 5;
    for (int o = 16; o > 0; o >>= 1) mx = fmaxf(mx, __shfl_xor_sync(0xffffffffu, mx, o));
    if (lane == 0) sh[w] = mx;
    __syncthreads();
    if (w == 0) {
        mx = (lane < 8) ? sh[lane] : -1e30f;
        for (int o = 16; o > 0; o >>= 1) mx = fmaxf(mx, __shfl_xor_sync(0xffffffffu, mx, o));
        if (lane == 0) sh[0] = mx;
    }
    __syncthreads();
    mx = sh[0];
    float tot = 0.f;
#pragma unroll
    for (int u = 0; u < 6; u++) {
        vals[u] = expf(vals[u] - mx);
        tot += vals[u];
    }
    __syncthreads();
    for (int o = 16; o > 0; o >>= 1) tot += __shfl_xor_sync(0xffffffffu, tot, o);
    if (lane == 0) sh[w] = tot;
    __syncthreads();
    if (w == 0) {
        tot = (lane < 8) ? sh[lane] : 0.f;
        for (int o = 16; o > 0; o >>= 1) tot += __shfl_xor_sync(0xffffffffu, tot, o);
        if (lane == 0) sh[0] = tot;
    }
    __syncthreads();
    float inv = 1.f / sh[0];
#pragma unroll
    for (int u = 0; u < 6; u++) crow[t + u * 256] = vals[u] * inv;
}

// ---------------- host orchestration ----------------
static void gemm(const float* A, const float* B, float* C, int M, int N, int Kd,
                 int lda, int ldb, int ldc,
                 long long aB, long long bB, long long cB, int batch, bool transB,
                 const float* bias, const float* resid, int relu, float alpha) {
    static bool attr_set = false;
    if (!attr_set) {
        cudaFuncSetAttribute(gemm_kernel<false>,
                             cudaFuncAttributeMaxDynamicSharedMemorySize, GSMEM_BYTES);
        cudaFuncSetAttribute(gemm_kernel<true>,
                             cudaFuncAttributeMaxDynamicSharedMemorySize, GSMEM_BYTES);
        attr_set = true;
    }
    dim3 grid((N + 127) / 128, (M + 127) / 128, batch);
    if (transB)
        gemm_kernel<true><<<grid, 256, GSMEM_BYTES>>>(A, B, C, M, N, Kd, lda, ldb, ldc,
                                                      aB, bB, cB, bias, resid, relu, alpha);
    else
        gemm_kernel<false><<<grid, 256, GSMEM_BYTES>>>(A, B, C, M, N, Kd, lda, ldb, ldc,
                                                       aB, bB, cB, bias, resid, relu, alpha);
}

extern "C" void kernel_launch(void* const* d_in, const int* in_sizes, int n_in,
                              void* d_out, int out_size) {
    const float* x    = (const float*)d_in[0];
    const float* ln1g = (const float*)d_in[1];
    const float* ln1b = (const float*)d_in[2];
    const float* ln2g = (const float*)d_in[3];
    const float* ln2b = (const float*)d_in[4];
    const float* Wq   = (const float*)d_in[5];
    const float* Wk   = (const float*)d_in[6];
    const float* Wv   = (const float*)d_in[7];
    const float* Wr   = (const float*)d_in[8];
    const float* Wo   = (const float*)d_in[9];
    const float* bo   = (const float*)d_in[10];
    const float* rwb  = (const float*)d_in[11];
    const float* rrb  = (const float*)d_in[12];
    const float* W1   = (const float*)d_in[13];
    const float* b1   = (const float*)d_in[14];
    const float* W2   = (const float*)d_in[15];
    const float* b2   = (const float*)d_in[16];
    float* out = (float*)d_out;

    auto sym = [](const auto& s) {
        void* p = nullptr;
        cudaGetSymbolAddress(&p, s);
        return (float*)p;
    };
    float* xn = sym(g_xn);
    float* q = sym(g_q);
    float* qrw = sym(g_qrw);
    float* qrr = sym(g_qrr);
    float* k = sym(g_k);
    float* v = sym(g_v);
    float* pos = sym(g_pos);
    float* rk = sym(g_rk);
    float* content = sym(g_content);
    float* rel = sym(g_rel);
    float* o = sym(g_o);
    float* y = sym(g_y);
    float* yn = sym(g_yn);
    float* h1 = sym(g_h1);

    // 1) LN1
    layernorm_kernel<<<Tn, 256>>>(x, ln1g, ln1b, xn);
    // 2) Q (scaled by K^-0.5), K, V projections
    gemm(xn, Wq, q, Tn, HK, Cn, Cn, HK, HK, 0, 0, 0, 1, false, nullptr, nullptr, 0, 0.125f);
    gemm(xn, Wk, k, Tn, HK, Cn, Cn, HK, HK, 0, 0, 0, 1, false, nullptr, nullptr, 0, 1.f);
    gemm(xn, Wv, v, Tn, HV, Cn, Cn, HV, HV, 0, 0, 0, 1, false, nullptr, nullptr, 0, 1.f);
    // 3) q + r_w_bias / r_r_bias
    qbias_kernel<<<(Tn * HK + 255) / 256, 256>>>(q, rwb, rrb, qrw, qrr);
    // 4) positional features + projection
    posfeat_kernel<<<L2, 32>>>(pos);
    gemm(pos, Wr, rk, L2, HK, Fn, Fn, HK, HK, 0, 0, 0, 1, false, nullptr, nullptr, 0, 1.f);
    // 5) content logits: per-head (q+rwb) @ k^T   [H,T,T]
    gemm(qrw, k, content, Tn, Tn, Kn, HK, HK, Tn, 64, 64, (long long)Tn * Tn, Hn, true,
         nullptr, nullptr, 0, 1.f);
    // 6) relative logits: per-head (q+rrb) @ r_k^T  [H,T,2T-1]
    gemm(qrr, rk, rel, Tn, L2, Kn, HK, HK, L2, 64, 64, (long long)Tn * L2, Hn, true,
         nullptr, nullptr, 0, 1.f);
    // 7) softmax with fused relative shift (attn written in-place into content)
    softmax_kernel<<<Hn * Tn, 256>>>(content, rel);
    // 8) attn @ v -> o [T, H*V]
    gemm(content, v, o, Tn, Vn, Tn, Tn, HV, HV, (long long)Tn * Tn, 192, 192, Hn, false,
         nullptr, nullptr, 0, 1.f);
    // 9) out proj + residual:  y = x + o @ Wo + bo
    gemm(o, Wo, y, Tn, Cn, HV, HV, Cn, Cn, 0, 0, 0, 1, false, bo, x, 0, 1.f);
    // 10) LN2 + MLP
    layernorm_kernel<<<Tn, 256>>>(y, ln2g, ln2b, yn);
    gemm(yn, W1, h1, Tn, 2 * Cn, Cn, Cn, 2 * Cn, 2 * Cn, 0, 0, 0, 1, false, b1, nullptr, 1, 1.f);
    gemm(h1, W2, out, Tn, Cn, 2 * Cn, 2 * Cn, Cn, Cn, 0, 0, 0, 1, false, b2, y, 0, 1.f);
}

// round 8
// speedup vs baseline: 2.4958x; 1.2188x over previous
#include <cuda_runtime.h>
#include <cuda_bf16.h>
#include <math.h>
#include <stdint.h>

// ---------------- problem constants ----------------
constexpr int Tn = 1536;
constexpr int Cn = 1536;
constexpr int Hn = 8;
constexpr int Kn = 64;
constexpr int Vn = 192;
constexpr int Fn = 192;
constexpr int HK = Hn * Kn;   // 512
constexpr int HV = Hn * Vn;   // 1536
constexpr int L2 = 2 * Tn - 1; // 3071

// ---------------- scratch (static device globals; no allocation) ----------------
__device__ float g_xn[Tn * Cn];
__device__ float g_q[Tn * HK];
__device__ float g_qrw[Tn * HK];
__device__ float g_qrr[Tn * HK];
__device__ float g_k[Tn * HK];
__device__ float g_v[Tn * HV];
__device__ float g_pos[L2 * Fn];
__device__ float g_rk[L2 * HK];
__device__ float g_content[(size_t)Hn * Tn * Tn];  // reused as attn (softmax in-place)
__device__ float g_rel[(size_t)Hn * Tn * L2];
__device__ float g_o[Tn * HV];
__device__ float g_y[Tn * Cn];
__device__ float g_yn[Tn * Cn];
__device__ float g_h1[Tn * 2 * Cn];

// ---------------- bf16 split-precision tensor-core GEMM (ldmatrix edition) ----------------
// C = alpha*A@op(B) (+bias)(+resid)(relu), fp32 in/out.
// x = hi + lo (bf16 each); C = Ahi*Bhi + Ahi*Blo + Alo*Bhi  (err ~2^-16/term).
// Tile 128x128, k-tile 32 fp32, 256 thr (8 warps 2m x 4n, warp tile 64x32),
// mma.sync.m16n8k16 with ldmatrix fragment loads.
// A smem: [128 m][72] bf16 rows; cols 0..31 = hi(k), 32..63 = lo(k). Pitch 144B.
// B NT smem: same layout indexed by n. B NN smem: [64 k][136] bf16 (rows 0..31 hi,
// 32..63 lo), cols = n (128 + pad). Pitch 272B. All LDSM phases conflict-free
// (row stride ≡ 16B * odd mod 128B).
// Batched via blockIdx.z (element strides). K%32==0 (64,192,512,1536,3072).
// NN requires N%16==0 (all NN call sites comply). NT predicates per row.
// winT != 0 enables the relative-logits window tile skip.
constexpr int APITCH = 72;                    // bf16
constexpr int ATILE = 128 * APITCH;           // bf16 elems / buf
constexpr int BPITCH_NN = 136;                // bf16
constexpr int BTILE_NN = 64 * BPITCH_NN;
constexpr int ATILE_B = ATILE * 2;            // bytes
constexpr int BTILE_NN_B = BTILE_NN * 2;
constexpr int GSMEM_BYTES = 4 * ATILE * 2;    // A[2] + B[2] (NT size >= NN size)

__device__ __forceinline__ uint32_t pack2bf(float x, float y) {
    __nv_bfloat162 h = __floats2bfloat162_rn(x, y);
    return *(uint32_t*)&h;
}

__device__ __forceinline__ void mma16816(float* c, const uint32_t* a,
                                         uint32_t b0, uint32_t b1) {
    asm volatile(
        "mma.sync.aligned.m16n8k16.row.col.f32.bf16.bf16.f32 "
        "{%0,%1,%2,%3}, {%4,%5,%6,%7}, {%8,%9}, {%0,%1,%2,%3};\n"
        : "+f"(c[0]), "+f"(c[1]), "+f"(c[2]), "+f"(c[3])
        : "r"(a[0]), "r"(a[1]), "r"(a[2]), "r"(a[3]), "r"(b0), "r"(b1));
}
__device__ __forceinline__ void ldsm4(uint32_t addr, uint32_t* r) {
    asm volatile("ldmatrix.sync.aligned.m8n8.x4.shared.b16 {%0,%1,%2,%3}, [%4];"
                 : "=r"(r[0]), "=r"(r[1]), "=r"(r[2]), "=r"(r[3]) : "r"(addr));
}
__device__ __forceinline__ void ldsm4t(uint32_t addr, uint32_t* r) {
    asm volatile("ldmatrix.sync.aligned.m8n8.x4.trans.shared.b16 {%0,%1,%2,%3}, [%4];"
                 : "=r"(r[0]), "=r"(r[1]), "=r"(r[2]), "=r"(r[3]) : "r"(addr));
}

template <bool TRANSB>
__global__ __launch_bounds__(256)
void gemm_kernel(const float* __restrict__ Ag, const float* __restrict__ Bg,
                 float* __restrict__ Cg, int M, int N, int Kd,
                 int lda, int ldb, int ldc,
                 long long aB, long long bB, long long cB,
                 const float* __restrict__ bias,
                 const float* __restrict__ resid,
                 int relu, float alpha, int winT) {
    const int m0 = blockIdx.y * 128;
    const int n0 = blockIdx.x * 128;
    if (winT) {  // relative-shift window: skip tiles the softmax never reads
        if (n0 + 127 < winT - 1 - (m0 + 127) || n0 > 2 * winT - 2 - m0) return;
    }

    extern __shared__ __nv_bfloat16 sm[];
    __nv_bfloat16* Asm = sm;                       // [2][128][APITCH]
    __nv_bfloat16* Bsm = sm + 2 * ATILE;           // NT: [2][128][APITCH]; NN: [2][64][BPITCH_NN]
    const uint32_t smem0 = (uint32_t)__cvta_generic_to_shared(sm);
    const uint32_t Ab0 = smem0;
    const uint32_t Bb0 = smem0 + 2 * ATILE_B;

    const float* A = Ag + (long long)blockIdx.z * aB;
    const float* B = Bg + (long long)blockIdx.z * bB;
    float* C = Cg + (long long)blockIdx.z * cB;

    const int tid = threadIdx.x;
    const int lane = tid & 31;
    const int warp = tid >> 5;
    const int wm = warp & 1;     // m offset wm*64
    const int wn = warp >> 1;    // n offset wn*32
    const int g = lane >> 2;
    const int th = lane & 3;

    // ldmatrix lane address components
    const int lA_row = lane & 15;
    const int lA_col = (lane >> 4) * 8;
    const int lB_row = ((lane >> 4) * 8) + (lane & 7);      // NT
    const int lB_col = ((lane >> 3) & 1) * 8;               // NT
    const int lBt_row = ((lane >> 3) & 1) * 8 + (lane & 7); // NN (trans)
    const int lBt_col = (lane >> 4) * 8;                    // NN (trans)

    // global load mappings (16 consecutive floats per thread)
    const int arow = tid >> 1;               // 0..127
    const int acol = (tid & 1) * 16;         // 0 or 16
    const int bkr = tid >> 3;                // 0..31  (NN)
    const int bnq = (tid & 7) * 16;          // 0..112 (NN)

    float acc[4][4][4];
#pragma unroll
    for (int i = 0; i < 4; i++)
#pragma unroll
        for (int j = 0; j < 4; j++)
#pragma unroll
            for (int c = 0; c < 4; c++) acc[i][j][c] = 0.f;

    const float4 zero4 = make_float4(0.f, 0.f, 0.f, 0.f);
    float4 va[4], vb[4];

    auto loadA = [&](int k0) {
        int gm = m0 + arow;
        if (gm < M) {
            const float4* p = (const float4*)(A + (long long)gm * lda + k0 + acol);
#pragma unroll
            for (int q = 0; q < 4; q++) va[q] = p[q];
        } else {
#pragma unroll
            for (int q = 0; q < 4; q++) va[q] = zero4;
        }
    };
    auto loadB = [&](int k0) {
        if (!TRANSB) {
            int gn = n0 + bnq;   // N%16==0: chunk all-in or all-out
            if (gn < N) {
                const float4* p = (const float4*)(B + (long long)(k0 + bkr) * ldb + gn);
#pragma unroll
                for (int q = 0; q < 4; q++) vb[q] = p[q];
            } else {
#pragma unroll
                for (int q = 0; q < 4; q++) vb[q] = zero4;
            }
        } else {
            int gn = n0 + arow;
            if (gn < N) {
                const float4* p = (const float4*)(B + (long long)gn * ldb + k0 + acol);
#pragma unroll
                for (int q = 0; q < 4; q++) vb[q] = p[q];
            } else {
#pragma unroll
                for (int q = 0; q < 4; q++) vb[q] = zero4;
            }
        }
    };
    auto splitpack = [](float x, float y, uint32_t& hi, uint32_t& lo) {
        __nv_bfloat16 hx = __float2bfloat16(x), hy = __float2bfloat16(y);
        float lx = x - __bfloat162float(hx), ly = y - __bfloat162float(hy);
        __nv_bfloat162 hh;
        hh.x = hx; hh.y = hy;
        hi = *(uint32_t*)&hh;
        lo = pack2bf(lx, ly);
    };
    // pack 16 floats into hi[8]/lo[8] and store as 2+2 uint4
    auto pack16 = [&](const float4* v, uint4* H, uint4* L) {
        uint32_t h[8], l[8];
        const float* f = (const float*)v;
#pragma unroll
        for (int i = 0; i < 8; i++) splitpack(f[2 * i], f[2 * i + 1], h[i], l[i]);
        H[0] = make_uint4(h[0], h[1], h[2], h[3]);
        H[1] = make_uint4(h[4], h[5], h[6], h[7]);
        L[0] = make_uint4(l[0], l[1], l[2], l[3]);
        L[1] = make_uint4(l[4], l[5], l[6], l[7]);
    };
    auto storeA = [&](int buf) {
        uint4 H[2], L[2];
        pack16(va, H, L);
        __nv_bfloat16* base = Asm + buf * ATILE + arow * APITCH;
        *(uint4*)(base + acol) = H[0];
        *(uint4*)(base + acol + 8) = H[1];
        *(uint4*)(base + 32 + acol) = L[0];
        *(uint4*)(base + 32 + acol + 8) = L[1];
    };
    auto storeB = [&](int buf) {
        uint4 H[2], L[2];
        pack16(vb, H, L);
        if (!TRANSB) {
            __nv_bfloat16* base = Bsm + buf * BTILE_NN;
            *(uint4*)(base + bkr * BPITCH_NN + bnq) = H[0];
            *(uint4*)(base + bkr * BPITCH_NN + bnq + 8) = H[1];
            *(uint4*)(base + (32 + bkr) * BPITCH_NN + bnq) = L[0];
            *(uint4*)(base + (32 + bkr) * BPITCH_NN + bnq + 8) = L[1];
        } else {
            __nv_bfloat16* base = Bsm + buf * ATILE + arow * APITCH;
            *(uint4*)(base + acol) = H[0];
            *(uint4*)(base + acol + 8) = H[1];
            *(uint4*)(base + 32 + acol) = L[0];
            *(uint4*)(base + 32 + acol + 8) = L[1];
        }
    };

    auto compute = [&](int buf) {
        const uint32_t Ab = Ab0 + buf * ATILE_B;
        const uint32_t Bb = TRANSB ? (Bb0 + buf * ATILE_B) : (Bb0 + buf * BTILE_NN_B);
#pragma unroll
        for (int k16 = 0; k16 < 32; k16 += 16) {
            uint32_t ah[4][4], al[4][4], bh[2][4], bl[2][4];
#pragma unroll
            for (int i = 0; i < 4; i++) {
                uint32_t r = Ab + (uint32_t)((wm * 64 + i * 16 + lA_row) * APITCH) * 2;
                ldsm4(r + (uint32_t)(k16 + lA_col) * 2, ah[i]);
                ldsm4(r + (uint32_t)(32 + k16 + lA_col) * 2, al[i]);
            }
            if (!TRANSB) {
#pragma unroll
                for (int j2 = 0; j2 < 2; j2++) {
                    uint32_t cbyte = (uint32_t)(wn * 32 + j2 * 16 + lBt_col) * 2;
                    ldsm4t(Bb + (uint32_t)((k16 + lBt_row) * BPITCH_NN) * 2 + cbyte, bh[j2]);
                    ldsm4t(Bb + (uint32_t)((32 + k16 + lBt_row) * BPITCH_NN) * 2 + cbyte, bl[j2]);
                }
            } else {
#pragma unroll
                for (int j2 = 0; j2 < 2; j2++) {
                    uint32_t r = Bb + (uint32_t)((wn * 32 + j2 * 16 + lB_row) * APITCH) * 2;
                    ldsm4(r + (uint32_t)(k16 + lB_col) * 2, bh[j2]);
                    ldsm4(r + (uint32_t)(32 + k16 + lB_col) * 2, bl[j2]);
                }
            }
#pragma unroll
            for (int i = 0; i < 4; i++)
#pragma unroll
                for (int j2 = 0; j2 < 2; j2++)
#pragma unroll
                    for (int sub = 0; sub < 2; sub++) {
                        int jj = j2 * 2 + sub;
                        mma16816(acc[i][jj], ah[i], bh[j2][sub * 2], bh[j2][sub * 2 + 1]);
                        mma16816(acc[i][jj], ah[i], bl[j2][sub * 2], bl[j2][sub * 2 + 1]);
                        mma16816(acc[i][jj], al[i], bh[j2][sub * 2], bh[j2][sub * 2 + 1]);
                    }
        }
    };

    loadA(0); loadB(0);
    storeA(0); storeB(0);
    __syncthreads();
    int buf = 0;
    for (int k0 = 32; k0 < Kd; k0 += 32) {
        loadA(k0); loadB(k0);
        compute(buf);
        storeA(buf ^ 1); storeB(buf ^ 1);
        __syncthreads();
        buf ^= 1;
    }
    compute(buf);

    // ---- epilogue ----
#pragma unroll
    for (int i = 0; i < 4; i++) {
        int rbase = m0 + wm * 64 + i * 16 + g;
#pragma unroll
        for (int j = 0; j < 4; j++) {
            int cbase = n0 + wn * 32 + j * 8 + th * 2;
#pragma unroll
            for (int c = 0; c < 4; c++) {
                int gm = rbase + (c >> 1) * 8;
                int gn = cbase + (c & 1);
                if (gm >= M || gn >= N) continue;
                float v = acc[i][j][c] * alpha;
                if (bias) v += bias[gn];
                if (resid) v += resid[(long long)gm * ldc + gn];
                if (relu) v = fmaxf(v, 0.f);
                C[(long long)gm * ldc + gn] = v;
            }
        }
    }
}

// ---------------- LayerNorm (one block per row) ----------------
__global__ void layernorm_kernel(const float* __restrict__ x, const float* __restrict__ g,
                                 const float* __restrict__ b, float* __restrict__ out) {
    int row = blockIdx.x;
    const float* xr = x + (long long)row * Cn;
    float s = 0.f, ss = 0.f;
    for (int i = threadIdx.x; i < Cn; i += blockDim.x) {
        float v = xr[i];
        s += v;
        ss += v * v;
    }
    __shared__ float shs[32], shss[32];
    int lane = threadIdx.x & 31, w = threadIdx.x >> 5;
    for (int o = 16; o > 0; o >>= 1) {
        s += __shfl_xor_sync(0xffffffffu, s, o);
        ss += __shfl_xor_sync(0xffffffffu, ss, o);
    }
    if (lane == 0) { shs[w] = s; shss[w] = ss; }
    __syncthreads();
    int nw = blockDim.x >> 5;
    if (w == 0) {
        s = (lane < nw) ? shs[lane] : 0.f;
        ss = (lane < nw) ? shss[lane] : 0.f;
        for (int o = 16; o > 0; o >>= 1) {
            s += __shfl_xor_sync(0xffffffffu, s, o);
            ss += __shfl_xor_sync(0xffffffffu, ss, o);
        }
        if (lane == 0) { shs[0] = s; shss[0] = ss; }
    }
    __syncthreads();
    float mean = shs[0] / Cn;
    float var = shss[0] / Cn - mean * mean;
    float inv = rsqrtf(var + 1e-3f);
    float* orow = out + (long long)row * Cn;
    for (int i = threadIdx.x; i < Cn; i += blockDim.x)
        orow[i] = (xr[i] - mean) * inv * g[i] + b[i];
}

// ---------------- q + biases ----------------
__global__ void qbias_kernel(const float* __restrict__ q, const float* __restrict__ rwb,
                             const float* __restrict__ rrb, float* __restrict__ qrw,
                             float* __restrict__ qrr) {
    int idx = blockIdx.x * blockDim.x + threadIdx.x;
    if (idx < Tn * HK) {
        int c = idx % HK;
        float v = q[idx];
        qrw[idx] = v + rwb[c];
        qrr[idx] = v + rrb[c];
    }
}

// ---------------- positional features (block per position, 32 threads) ----------------
__global__ void posfeat_kernel(float* __restrict__ pos) {
    int l = blockIdx.x;       // 0..3070
    int i = threadIdx.x;      // 0..31
    float d = (float)(l - (Tn - 1));
    float ap = fabsf(d);

    double start = 3.0, stop = log2((double)Tn);
    float hl = (float)exp2(start + (stop - start) * ((double)i / 31.0));
    float coef = (float)(-(log(2.0) / (double)hl));
    float fe = expf(ap * coef);

    float width = exp2f((float)(i + 1)) - 1.0f;
    float fcm = (width > ap) ? 1.f : 0.f;

    // gamma pdf bumps. xlogy(c-1, 0) = -inf -> prob = 1e-8 at ap=0 (do NOT guard).
    float conc = 4.0f * (float)((i + 1) * (i + 1));
    float rate = (float)(((double)(i + 1)) / 12.0);
    float log_unnorm = (conc - 1.0f) * logf(ap) - rate * ap;
    float log_norm = lgammaf(conc) - conc * logf(rate);
    float prob = expf(log_unnorm - log_norm) + 1e-8f;

    float mx = prob;
    for (int o = 16; o > 0; o >>= 1) mx = fmaxf(mx, __shfl_xor_sync(0xffffffffu, mx, o));
    float fg = prob / mx;

    float sg = (d > 0.f) ? 1.f : ((d < 0.f) ? -1.f : 0.f);
    float* row = pos + (long long)l * Fn;
    row[i] = fe;
    row[32 + i] = fcm;
    row[64 + i] = fg;
    row[96 + i] = sg * fe;
    row[128 + i] = sg * fcm;
    row[160 + i] = sg * fg;
}

// ---------------- softmax with fused relative shift (in-place on content) ----------------
__global__ void softmax_kernel(float* __restrict__ content, const float* __restrict__ rel) {
    int h = blockIdx.x / Tn, q = blockIdx.x % Tn;
    float* crow = content + ((long long)h * Tn + q) * Tn;
    const float* rrow = rel + ((long long)h * Tn + q) * (long long)L2 + (Tn - 1 - q);
    int t = threadIdx.x;  // 256 threads, 6 elems each
    float vals[6];
    float mx = -1e30f;
#pragma unroll
    for (int u = 0; u < 6; u++) {
        int m = t + u * 256;
        float v = crow[m] + rrow[m];
        vals[u] = v;
        mx = fmaxf(mx, v);
    }
    __shared__ float sh[32];
    int lane = t & 31, w = t >> 5;
    for (int o = 16; o > 0; o >>= 1) mx = fmaxf(mx, __shfl_xor_sync(0xffffffffu, mx, o));
    if (lane == 0) sh[w] = mx;
    __syncthreads();
    if (w == 0) {
        mx = (lane < 8) ? sh[lane] : -1e30f;
        for (int o = 16; o > 0; o >>= 1) mx = fmaxf(mx, __shfl_xor_sync(0xffffffffu, mx, o));
        if (lane == 0) sh[0] = mx;
    }
    __syncthreads();
    mx = sh[0];
    float tot = 0.f;
#pragma unroll
    for (int u = 0; u < 6; u++) {
        vals[u] = expf(vals[u] - mx);
        tot += vals[u];
    }
    __syncthreads();
    for (int o = 16; o > 0; o >>= 1) tot += __shfl_xor_sync(0xffffffffu, tot, o);
    if (lane == 0) sh[w] = tot;
    __syncthreads();
    if (w == 0) {
        tot = (lane < 8) ? sh[lane] : 0.f;
        for (int o = 16; o > 0; o >>= 1) tot += __shfl_xor_sync(0xffffffffu, tot, o);
        if (lane == 0) sh[0] = tot;
    }
    __syncthreads();
    float inv = 1.f / sh[0];
#pragma unroll
    for (int u = 0; u < 6; u++) crow[t + u * 256] = vals[u] * inv;
}

// ---------------- host orchestration ----------------
static void gemm(const float* A, const float* B, float* C, int M, int N, int Kd,
                 int lda, int ldb, int ldc,
                 long long aB, long long bB, long long cB, int batch, bool transB,
                 const float* bias, const float* resid, int relu, float alpha,
                 int winT = 0) {
    static bool attr_set = false;
    if (!attr_set) {
        cudaFuncSetAttribute(gemm_kernel<false>,
                             cudaFuncAttributeMaxDynamicSharedMemorySize, GSMEM_BYTES);
        cudaFuncSetAttribute(gemm_kernel<true>,
                             cudaFuncAttributeMaxDynamicSharedMemorySize, GSMEM_BYTES);
        attr_set = true;
    }
    dim3 grid((N + 127) / 128, (M + 127) / 128, batch);
    if (transB)
        gemm_kernel<true><<<grid, 256, GSMEM_BYTES>>>(A, B, C, M, N, Kd, lda, ldb, ldc,
                                                      aB, bB, cB, bias, resid, relu, alpha, winT);
    else
        gemm_kernel<false><<<grid, 256, GSMEM_BYTES>>>(A, B, C, M, N, Kd, lda, ldb, ldc,
                                                       aB, bB, cB, bias, resid, relu, alpha, winT);
}

extern "C" void kernel_launch(void* const* d_in, const int* in_sizes, int n_in,
                              void* d_out, int out_size) {
    const float* x    = (const float*)d_in[0];
    const float* ln1g = (const float*)d_in[1];
    const float* ln1b = (const float*)d_in[2];
    const float* ln2g = (const float*)d_in[3];
    const float* ln2b = (const float*)d_in[4];
    const float* Wq   = (const float*)d_in[5];
    const float* Wk   = (const float*)d_in[6];
    const float* Wv   = (const float*)d_in[7];
    const float* Wr   = (const float*)d_in[8];
    const float* Wo   = (const float*)d_in[9];
    const float* bo   = (const float*)d_in[10];
    const float* rwb  = (const float*)d_in[11];
    const float* rrb  = (const float*)d_in[12];
    const float* W1   = (const float*)d_in[13];
    const float* b1   = (const float*)d_in[14];
    const float* W2   = (const float*)d_in[15];
    const float* b2   = (const float*)d_in[16];
    float* out = (float*)d_out;

    auto sym = [](const auto& s) {
        void* p = nullptr;
        cudaGetSymbolAddress(&p, s);
        return (float*)p;
    };
    float* xn = sym(g_xn);
    float* q = sym(g_q);
    float* qrw = sym(g_qrw);
    float* qrr = sym(g_qrr);
    float* k = sym(g_k);
    float* v = sym(g_v);
    float* pos = sym(g_pos);
    float* rk = sym(g_rk);
    float* content = sym(g_content);
    float* rel = sym(g_rel);
    float* o = sym(g_o);
    float* y = sym(g_y);
    float* yn = sym(g_yn);
    float* h1 = sym(g_h1);

    // 1) LN1
    layernorm_kernel<<<Tn, 256>>>(x, ln1g, ln1b, xn);
    // 2) Q (scaled by K^-0.5), K, V projections
    gemm(xn, Wq, q, Tn, HK, Cn, Cn, HK, HK, 0, 0, 0, 1, false, nullptr, nullptr, 0, 0.125f);
    gemm(xn, Wk, k, Tn, HK, Cn, Cn, HK, HK, 0, 0, 0, 1, false, nullptr, nullptr, 0, 1.f);
    gemm(xn, Wv, v, Tn, HV, Cn, Cn, HV, HV, 0, 0, 0, 1, false, nullptr, nullptr, 0, 1.f);
    // 3) q + r_w_bias / r_r_bias
    qbias_kernel<<<(Tn * HK + 255) / 256, 256>>>(q, rwb, rrb, qrw, qrr);
    // 4) positional features + projection
    posfeat_kernel<<<L2, 32>>>(pos);
    gemm(pos, Wr, rk, L2, HK, Fn, Fn, HK, HK, 0, 0, 0, 1, false, nullptr, nullptr, 0, 1.f);
    // 5) content logits: per-head (q+rwb) @ k^T   [H,T,T]
    gemm(qrw, k, content, Tn, Tn, Kn, HK, HK, Tn, 64, 64, (long long)Tn * Tn, Hn, true,
         nullptr, nullptr, 0, 1.f);
    // 6) relative logits: per-head (q+rrb) @ r_k^T  [H,T,2T-1], window-skipped
    gemm(qrr, rk, rel, Tn, L2, Kn, HK, HK, L2, 64, 64, (long long)Tn * L2, Hn, true,
         nullptr, nullptr, 0, 1.f, Tn);
    // 7) softmax with fused relative shift (attn written in-place into content)
    softmax_kernel<<<Hn * Tn, 256>>>(content, rel);
    // 8) attn @ v -> o [T, H*V]
    gemm(content, v, o, Tn, Vn, Tn, Tn, HV, HV, (long long)Tn * Tn, 192, 192, Hn, false,
         nullptr, nullptr, 0, 1.f);
    // 9) out proj + residual:  y = x + o @ Wo + bo
    gemm(o, Wo, y, Tn, Cn, HV, HV, Cn, Cn, 0, 0, 0, 1, false, bo, x, 0, 1.f);
    // 10) LN2 + MLP
    layernorm_kernel<<<Tn, 256>>>(y, ln2g, ln2b, yn);
    gemm(yn, W1, h1, Tn, 2 * Cn, Cn, Cn, 2 * Cn, 2 * Cn, 0, 0, 0, 1, false, b1, nullptr, 1, 1.f);
    gemm(h1, W2, out, Tn, Cn, 2 * Cn, 2 * Cn, Cn, Cn, 0, 0, 0, 1, false, b2, y, 0, 1.f);
}